// round 7
// baseline (speedup 1.0000x reference)
#include <cuda_runtime.h>
#include <math.h>

// ----------------------------------------------------------------------------
// Strict2_5DLoss — single persistent kernel, v3: warpgroup consumers.
// 1184 independent 128-thread consumers (2 per block). Tasks 0..767 are
// (b,g,lvl) pair tasks, 768..1439 are 1024-cell dense objectness chunks.
// Consumer c starts statically on task c (no initial queue trip); a global
// queue (init 1184) serves the 256 leftover dense chunks to early finishers.
// Pair task: bbox scan on squared segment distances (sqrt only for prefiltered
// cells, preserving the reference's sqrt-rounded tie structure), candidates
// packed (dist_bits<<32)|idx in per-group smem, rank top-64 select, direct
// reg/cls/pos accumulation; objectness via per-unique-cell correction with an
// atomicOr dedup bitmask. Dense softplus uses product batching (1 LG2 / 8
// cells). Grid barrier; block 0 reduces partials; others clear the bitmask;
// exit barrier resets the queue for graph-replay determinism.
// ----------------------------------------------------------------------------

#define NT    256
#define GRID  592
#define NCONS (2 * GRID)             // 1184 warpgroup consumers
#define CAP   2048
#define NPAIR 768
#define DCH   672                    // 672 * 1024 = 688128
#define NTASK (NPAIR + DCH)          // 1440
#define TOTAL_CELLS 688128
#define NBITS (TOTAL_CELLS / 32)

__device__ int g_task = NCONS;       // queue begins after static assignment
__device__ int g_arrive = 0, g_exit = 0;
__device__ unsigned g_bits[NBITS];   // zero-init; cleared every run
__device__ double g_part[GRID][5];   // reg, cls, obj, pos, posnow

__device__ __forceinline__ float fast_sp(float x) {   // softplus via MUFU
    return fmaxf(x, 0.0f) + __logf(1.0f + __expf(-fabsf(x)));
}

__device__ __forceinline__ void grp_bar(int grp) {
    asm volatile("bar.sync %0, %1;" :: "r"(grp + 1), "r"(128) : "memory");
}

__global__ void __launch_bounds__(NT, 4)
fused_kernel(const float* __restrict__ reg0, const float* __restrict__ obj0,
             const float* __restrict__ cls0,
             const float* __restrict__ reg1, const float* __restrict__ obj1,
             const float* __restrict__ cls1,
             const float* __restrict__ reg2, const float* __restrict__ obj2,
             const float* __restrict__ cls2,
             const float* __restrict__ gt, float* __restrict__ out) {
    __shared__ unsigned long long s_key[2][CAP];
    __shared__ int    s_task[2], s_count[2];
    __shared__ float  s_gt[1536];            // full gt tensor (8*32*6)
    __shared__ double s_w[8][5];

    const int tid  = threadIdx.x;
    const int bid  = blockIdx.x;
    const int wid  = tid >> 5;
    const int lane = tid & 31;
    const int grp  = tid >> 7;               // warpgroup 0/1
    const int gtid = tid & 127;

    // preload gt (removes gmem latency from every pair task)
    for (int i = tid; i < 1536; i += NT) s_gt[i] = gt[i];
    __syncthreads();

    double acc[5];  // 0:reg 1:cls 2:obj 3:pos 4:posnow
#pragma unroll
    for (int c = 0; c < 5; c++) acc[c] = 0.0;

    // ================= Phase 1: task loop =================
    int t = bid * 2 + grp;                   // static first task
    for (;;) {
        if (t >= NTASK) break;

        if (t >= NPAIR) {
            // ---- dense objectness chunk: 1024 cells, product-batched ----
            int base = (t - NPAIR) * 1024;
            const float* src; int off;
            if (base < 524288)      { src = obj0; off = base; }
            else if (base < 655360) { src = obj1; off = base - 524288; }
            else                    { src = obj2; off = base - 655360; }
            const float4* s4 = (const float4*)(src + off);
            float mx = 0.0f, prod = 1.0f;
#pragma unroll
            for (int k = 0; k < 2; k++) {
                float4 v = s4[gtid + k * 128];
                mx += fmaxf(v.x, 0.0f) + fmaxf(v.y, 0.0f)
                    + fmaxf(v.z, 0.0f) + fmaxf(v.w, 0.0f);
                prod *= (1.0f + __expf(-fabsf(v.x)))
                      * (1.0f + __expf(-fabsf(v.y)))
                      * (1.0f + __expf(-fabsf(v.z)))
                      * (1.0f + __expf(-fabsf(v.w)));
            }
            acc[2] += (double)(mx + __logf(prod));
        } else {
            // ---- pair task ----
            const int lvl = t >> 8;
            const int p   = t & 255;
            const int b   = p >> 5;
            const int g   = p & 31;
            const int lg  = 8 - lvl;
            const int Ws  = 1 << lg;
            const int HW  = Ws * Ws;
            const float st = (float)(8 << lvl);

            const float* reg = (lvl == 0) ? reg0 : (lvl == 1) ? reg1 : reg2;
            const float* cls = (lvl == 0) ? cls0 : (lvl == 1) ? cls1 : cls2;
            const float* obj = (lvl == 0) ? obj0 : (lvl == 1) ? obj1 : obj2;
            const int markBase =
                ((lvl == 0) ? 0 : (lvl == 1) ? 524288 : 655360) + b * HW;

            const float* gp = s_gt + (b * 32 + g) * 6;
            const float Ax = gp[0], Ay = gp[1];
            const float Bx = gp[2], By = gp[3];
            const float Cx = gp[4], Cy = gp[5];

            if (gtid == 0) s_count[grp] = 0;

            float minx = fminf(Ax, fminf(Bx, Cx)) - 3.0f;
            float maxx = fmaxf(Ax, fmaxf(Bx, Cx)) + 3.0f;
            float miny = fminf(Ay, fminf(By, Cy)) - 3.0f;
            float maxy = fmaxf(Ay, fmaxf(By, Cy)) + 3.0f;
            int ix0 = max(0,      (int)floorf(minx / st - 0.5f));
            int ix1 = min(Ws - 1, (int)floorf(maxx / st - 0.5f) + 1);
            int iy0 = max(0,      (int)floorf(miny / st - 0.5f));
            int iy1 = min(Ws - 1, (int)floorf(maxy / st - 0.5f) + 1);
            int nx = ix1 - ix0 + 1; if (nx < 0) nx = 0;
            int ny = iy1 - iy0 + 1; if (ny < 0) ny = 0;
            const int tot = nx * ny;
            const float rnx = __fdividef(1.0f, (float)nx);

            const float e0x = Bx - Ax, e0y = By - Ay;
            const float e1x = Cx - Bx, e1y = Cy - By;
            const float e2x = Ax - Cx, e2y = Ay - Cy;
            const float i0 = __fdividef(1.0f, e0x * e0x + e0y * e0y + 1e-9f);
            const float i1 = __fdividef(1.0f, e1x * e1x + e1y * e1y + 1e-9f);
            const float i2 = __fdividef(1.0f, e2x * e2x + e2y * e2y + 1e-9f);

            grp_bar(grp);   // s_count visible; prior select on s_key done

            for (int c = gtid; c < tot; c += 128) {
                int iy = (int)((float)c * rnx);
                int ix = c - iy * nx;
                if (ix < 0) { iy--; ix += nx; }
                else if (ix >= nx) { iy++; ix -= nx; }
                ix += ix0; iy += iy0;
                float px = (ix + 0.5f) * st;
                float py = (iy + 0.5f) * st;

                float d1 = (px - Bx) * (Ay - By) - (Ax - Bx) * (py - By);
                float d2 = (px - Cx) * (By - Cy) - (Bx - Cx) * (py - Cy);
                float d3 = (px - Ax) * (Cy - Ay) - (Cx - Ax) * (py - Ay);
                bool hneg = (d1 < 0.0f) || (d2 < 0.0f) || (d3 < 0.0f);
                bool hpos = (d1 > 0.0f) || (d2 > 0.0f) || (d3 > 0.0f);
                bool inside = !(hneg && hpos);

                float wx = px - Ax, wy = py - Ay;
                float tt = fminf(fmaxf((wx * e0x + wy * e0y) * i0, 0.0f), 1.0f);
                float dx = wx - tt * e0x, dy = wy - tt * e0y;
                float dd = dx * dx + dy * dy;
                wx = px - Bx; wy = py - By;
                tt = fminf(fmaxf((wx * e1x + wy * e1y) * i1, 0.0f), 1.0f);
                dx = wx - tt * e1x; dy = wy - tt * e1y;
                dd = fminf(dd, dx * dx + dy * dy);
                wx = px - Cx; wy = py - Cy;
                tt = fminf(fmaxf((wx * e2x + wy * e2y) * i2, 0.0f), 1.0f);
                dx = wx - tt * e2x; dy = wy - tt * e2y;
                dd = fminf(dd, dx * dx + dy * dy);

                if (inside || dd <= 9.00001f) {
                    float dist = sqrtf(dd + 1e-12f);   // exact: matches ref
                    if (inside || dist <= 3.0f) {
                        int slot = atomicAdd(&s_count[grp], 1);
                        if (slot < CAP)
                            s_key[grp][slot] =
                                ((unsigned long long)__float_as_uint(dist) << 32)
                                | (unsigned)(iy * Ws + ix);
                    }
                }
            }
            grp_bar(grp);
            const int count = min(s_count[grp], CAP);
            const float inv = 1.0f / st;

            float regA = 0.0f, clsA = 0.0f, objA = 0.0f;
            int nv = 0, nn = 0;

            for (int e = gtid; e < count; e += 128) {
                const unsigned long long ke = s_key[grp][e];
                bool sel = true;
                if (count > 64) {
                    int rank = 0;
                    for (int j = 0; j < count; j++)
                        rank += (s_key[grp][j] < ke);
                    sel = (rank < 64);
                }
                if (sel) {
                    const int ie = (int)(ke & 0xffffffffu);
                    nv++;
                    clsA += fast_sp(-cls[(size_t)b * HW + ie]);

                    int ix = ie & (Ws - 1), iy = ie >> lg;
                    float ax = (ix + 0.5f) * st;
                    float ay = (iy + 0.5f) * st;
                    float g0x = (Ax - ax) * inv, g0y = (Ay - ay) * inv;
                    float g1x = (Bx - ax) * inv, g1y = (By - ay) * inv;
                    float g2x = (Cx - ax) * inv, g2y = (Cy - ay) * inv;

                    const float* rb = reg + (size_t)b * 6 * HW + ie;
                    float p0x = fminf(fmaxf(rb[0],            -64.0f), 64.0f);
                    float p0y = fminf(fmaxf(rb[(size_t)HW],   -64.0f), 64.0f);
                    float p1x = fminf(fmaxf(rb[(size_t)2*HW], -64.0f), 64.0f);
                    float p1y = fminf(fmaxf(rb[(size_t)3*HW], -64.0f), 64.0f);
                    float p2x = fminf(fmaxf(rb[(size_t)4*HW], -64.0f), 64.0f);
                    float p2y = fminf(fmaxf(rb[(size_t)5*HW], -64.0f), 64.0f);

                    float p0 = (p0x - g0x) * (p0x - g0x)
                             + (p0y - g0y) * (p0y - g0y);
                    float d11 = sqrtf((p1x-g1x)*(p1x-g1x) + (p1y-g1y)*(p1y-g1y));
                    float d12 = sqrtf((p1x-g2x)*(p1x-g2x) + (p1y-g2y)*(p1y-g2y));
                    float d21 = sqrtf((p2x-g1x)*(p2x-g1x) + (p2y-g1y)*(p2y-g1y));
                    float d22 = sqrtf((p2x-g2x)*(p2x-g2x) + (p2y-g2y)*(p2y-g2y));
                    float cd = fminf(d11, d12) + fminf(d21, d22)
                             + fminf(d11, d21) + fminf(d12, d22);
                    regA += p0 + cd;

                    int cell = markBase + ie;
                    unsigned bit = 1u << (cell & 31);
                    unsigned old = atomicOr(&g_bits[cell >> 5], bit);
                    if (!(old & bit)) {
                        float x = obj[(size_t)b * HW + ie];
                        objA += 1.2f * fast_sp(-x) - fast_sp(x);
                        nn++;
                    }
                }
            }
            acc[0] += (double)regA;
            acc[1] += (double)clsA;
            acc[2] += (double)objA;
            acc[3] += (double)nv;
            acc[4] += (double)nn;
        }

        // fetch next task (queue serves leftovers beyond static assignment)
        if (gtid == 0) s_task[grp] = atomicAdd(&g_task, 1);
        grp_bar(grp);   // also fences this task's s_key reads before reuse
        t = s_task[grp];
    }

    // ================= block reduce -> per-block partials =================
    __syncthreads();
#pragma unroll
    for (int c = 0; c < 5; c++) {
        double v = acc[c];
#pragma unroll
        for (int o = 16; o > 0; o >>= 1)
            v += __shfl_down_sync(0xffffffffu, v, o);
        if (lane == 0) s_w[wid][c] = v;
    }
    __syncthreads();
    if (wid == 0) {
#pragma unroll
        for (int c = 0; c < 5; c++) {
            double v = (lane < 8) ? s_w[lane][c] : 0.0;
#pragma unroll
            for (int o = 4; o > 0; o >>= 1)
                v += __shfl_down_sync(0xffffffffu, v, o);
            if (lane == 0) g_part[bid][c] = v;
        }
    }

    // ================= grid barrier =================
    if (tid == 0) {
        __threadfence();
        atomicAdd(&g_arrive, 1);
        while (*(volatile int*)&g_arrive < GRID) __nanosleep(32);
        __threadfence();
    }
    __syncthreads();

    // ================= Phase 2: finalize + cleanup =================
    if (bid == 0) {
        double v[5];
#pragma unroll
        for (int c = 0; c < 5; c++) v[c] = 0.0;
        for (int i = tid; i < GRID; i += NT)
#pragma unroll
            for (int c = 0; c < 5; c++) v[c] += g_part[i][c];
#pragma unroll
        for (int c = 0; c < 5; c++) {
            double r = v[c];
#pragma unroll
            for (int o = 16; o > 0; o >>= 1)
                r += __shfl_down_sync(0xffffffffu, r, o);
            if (lane == 0) s_w[wid][c] = r;
        }
        __syncthreads();
        if (tid == 0) {
            double tot[5];
#pragma unroll
            for (int c = 0; c < 5; c++) {
                double r = 0.0;
                for (int w = 0; w < 8; w++) r += s_w[w][c];
                tot[c] = r;
            }
            double pos_eps = fmax(tot[3], 1.0);
            double neg = fmax((double)TOTAL_CELLS - tot[4], 1.0);
            double total = tot[0] / pos_eps
                         + tot[2] / (pos_eps + neg)
                         + tot[1] / pos_eps;
            float tt = (float)total;
            out[0] = isfinite(tt) ? tt : 0.0f;
        }
    } else {
        for (int i = (bid - 1) * NT + tid; i < NBITS; i += (GRID - 1) * NT)
            g_bits[i] = 0u;
    }

    // ================= exit barrier: reset queue state =================
    __syncthreads();
    if (tid == 0) {
        __threadfence();
        int r = atomicAdd(&g_exit, 1);
        if (r == GRID - 1) { g_task = NCONS; g_arrive = 0; g_exit = 0; }
    }
}

extern "C" void kernel_launch(void* const* d_in, const int* in_sizes, int n_in,
                              void* d_out, int out_size) {
    (void)in_sizes; (void)n_in; (void)out_size;
    fused_kernel<<<GRID, NT>>>(
        (const float*)d_in[0], (const float*)d_in[1], (const float*)d_in[2],
        (const float*)d_in[3], (const float*)d_in[4], (const float*)d_in[5],
        (const float*)d_in[6], (const float*)d_in[7], (const float*)d_in[8],
        (const float*)d_in[9], (float*)d_out);
}

// round 9
// speedup vs baseline: 1.3708x; 1.3708x over previous
#include <cuda_runtime.h>
#include <math.h>

// ----------------------------------------------------------------------------
// Strict2_5DLoss — single persistent kernel, v4: histogram top-64 select.
// 592 blocks (256 thr) = dynamic consumers. Tasks 0..767: (b,g,lvl) pair
// tasks (lvl0 first); 768..1439: 1024-cell dense objectness chunks.
// Pair task: bbox scan on squared segment distances (sqrt only after d^2
// prefilter -> reference-exact sqrt-rounded keys), candidates packed as
// (dist_bits<<32)|idx u64 in smem, then O(count) two-level histogram select
// of the 64 smallest keys (identical set to stable top-k: u64 order ==
// (dist, idx) lex order). Objectness handled per-unique-cell via atomicOr
// dedup bitmask. Grid barrier; block 0 reduces partials; others clear the
// bitmask; exit barrier resets queue state for graph-replay determinism.
// ----------------------------------------------------------------------------

#define NT    256
#define GRID  592
#define CAP   2048
#define NPAIR 768
#define DCH   672                    // 672 * 1024 = 688128
#define NTASK (NPAIR + DCH)          // 1440
#define TOTAL_CELLS 688128
#define NBITS (TOTAL_CELLS / 32)

__device__ int g_task = GRID;        // queue starts after static assignment
__device__ int g_arrive = 0, g_exit = 0;
__device__ unsigned g_bits[NBITS];   // zero-init; cleared every run
__device__ double g_part[GRID][5];   // reg, cls, obj, pos, posnow

__device__ __forceinline__ float fast_sp(float x) {   // softplus via MUFU
    return fmaxf(x, 0.0f) + __logf(1.0f + __expf(-fabsf(x)));
}

// Warp-0 helper: given a 256-bin histogram, find the bin containing 0-based
// rank T and the count of keys in bins strictly below it.
__device__ __forceinline__ void pivot_from_hist(const int* hist, int T,
                                                int lane, int& bin, int& below) {
    int base = lane * 8, s = 0;
#pragma unroll
    for (int i = 0; i < 8; i++) s += hist[base + i];
    int pre = s;
#pragma unroll
    for (int o = 1; o < 32; o <<= 1) {
        int v = __shfl_up_sync(0xffffffffu, pre, o);
        if (lane >= o) pre += v;
    }
    int excl = pre - s;                       // exclusive prefix
    bool has = (excl <= T) && (T < pre);
    unsigned mk = __ballot_sync(0xffffffffu, has);
    int pl = __ffs((int)mk) - 1;
    int b = 0, c = 0;
    if (lane == pl) {
        c = excl; b = base;
        while (c + hist[b] <= T) { c += hist[b]; b++; }
    }
    bin   = __shfl_sync(0xffffffffu, b, pl);
    below = __shfl_sync(0xffffffffu, c, pl);
}

__global__ void __launch_bounds__(NT, 4)
fused_kernel(const float* __restrict__ reg0, const float* __restrict__ obj0,
             const float* __restrict__ cls0,
             const float* __restrict__ reg1, const float* __restrict__ obj1,
             const float* __restrict__ cls1,
             const float* __restrict__ reg2, const float* __restrict__ obj2,
             const float* __restrict__ cls2,
             const float* __restrict__ gt, float* __restrict__ out) {
    __shared__ unsigned long long s_key[CAP];
    __shared__ int    s_hist[256];
    __shared__ int    s_task, s_count, s_pb, s_n1, s_sb, s_n2;
    __shared__ float  s_gt[1536];             // full gt tensor (8*32*6)
    __shared__ double s_w[8][5];

    const int tid  = threadIdx.x;
    const int bid  = blockIdx.x;
    const int wid  = tid >> 5;
    const int lane = tid & 31;

    for (int i = tid; i < 1536; i += NT) s_gt[i] = gt[i];

    double acc[5];  // 0:reg 1:cls 2:obj 3:pos 4:posnow
#pragma unroll
    for (int c = 0; c < 5; c++) acc[c] = 0.0;

    __syncthreads();

    // ================= Phase 1: task loop =================
    int t = bid;                              // static first task
    for (;;) {
        if (t >= NTASK) break;

        if (t >= NPAIR) {
            // ---- dense objectness chunk: 1024 cells, product-batched ----
            int base = (t - NPAIR) * 1024;
            const float* src; int off;
            if (base < 524288)      { src = obj0; off = base; }
            else if (base < 655360) { src = obj1; off = base - 524288; }
            else                    { src = obj2; off = base - 655360; }
            const float4 v = ((const float4*)(src + off))[tid];
            float mx = fmaxf(v.x, 0.0f) + fmaxf(v.y, 0.0f)
                     + fmaxf(v.z, 0.0f) + fmaxf(v.w, 0.0f);
            float prod = (1.0f + __expf(-fabsf(v.x)))
                       * (1.0f + __expf(-fabsf(v.y)))
                       * (1.0f + __expf(-fabsf(v.z)))
                       * (1.0f + __expf(-fabsf(v.w)));
            acc[2] += (double)(mx + __logf(prod));
        } else {
            // ---- pair task (lvl0 first: t>>8) ----
            const int lvl = t >> 8;
            const int p   = t & 255;
            const int b   = p >> 5;
            const int g   = p & 31;
            const int lg  = 8 - lvl;
            const int Ws  = 1 << lg;
            const int HW  = Ws * Ws;
            const float st = (float)(8 << lvl);

            const float* reg = (lvl == 0) ? reg0 : (lvl == 1) ? reg1 : reg2;
            const float* cls = (lvl == 0) ? cls0 : (lvl == 1) ? cls1 : cls2;
            const float* obj = (lvl == 0) ? obj0 : (lvl == 1) ? obj1 : obj2;
            const int markBase =
                ((lvl == 0) ? 0 : (lvl == 1) ? 524288 : 655360) + b * HW;

            const float* gp = s_gt + (b * 32 + g) * 6;
            const float Ax = gp[0], Ay = gp[1];
            const float Bx = gp[2], By = gp[3];
            const float Cx = gp[4], Cy = gp[5];

            if (tid == 0) s_count = 0;

            float minx = fminf(Ax, fminf(Bx, Cx)) - 3.0f;
            float maxx = fmaxf(Ax, fmaxf(Bx, Cx)) + 3.0f;
            float miny = fminf(Ay, fminf(By, Cy)) - 3.0f;
            float maxy = fmaxf(Ay, fmaxf(By, Cy)) + 3.0f;
            int ix0 = max(0,      (int)floorf(minx / st - 0.5f));
            int ix1 = min(Ws - 1, (int)floorf(maxx / st - 0.5f) + 1);
            int iy0 = max(0,      (int)floorf(miny / st - 0.5f));
            int iy1 = min(Ws - 1, (int)floorf(maxy / st - 0.5f) + 1);
            int nx = ix1 - ix0 + 1; if (nx < 0) nx = 0;
            int ny = iy1 - iy0 + 1; if (ny < 0) ny = 0;
            const int tot = nx * ny;
            const float rnx = __fdividef(1.0f, (float)nx);

            const float e0x = Bx - Ax, e0y = By - Ay;
            const float e1x = Cx - Bx, e1y = Cy - By;
            const float e2x = Ax - Cx, e2y = Ay - Cy;
            const float i0 = __fdividef(1.0f, e0x * e0x + e0y * e0y + 1e-9f);
            const float i1 = __fdividef(1.0f, e1x * e1x + e1y * e1y + 1e-9f);
            const float i2 = __fdividef(1.0f, e2x * e2x + e2y * e2y + 1e-9f);

            __syncthreads();   // s_count visible; prior task's s_key reads done

            for (int c = tid; c < tot; c += NT) {
                int iy = (int)((float)c * rnx);
                int ix = c - iy * nx;
                if (ix < 0) { iy--; ix += nx; }
                else if (ix >= nx) { iy++; ix -= nx; }
                ix += ix0; iy += iy0;
                float px = (ix + 0.5f) * st;
                float py = (iy + 0.5f) * st;

                float d1 = (px - Bx) * (Ay - By) - (Ax - Bx) * (py - By);
                float d2 = (px - Cx) * (By - Cy) - (Bx - Cx) * (py - Cy);
                float d3 = (px - Ax) * (Cy - Ay) - (Cx - Ax) * (py - Ay);
                bool hneg = (d1 < 0.0f) || (d2 < 0.0f) || (d3 < 0.0f);
                bool hpos = (d1 > 0.0f) || (d2 > 0.0f) || (d3 > 0.0f);
                bool inside = !(hneg && hpos);

                float wx = px - Ax, wy = py - Ay;
                float tt = fminf(fmaxf((wx * e0x + wy * e0y) * i0, 0.0f), 1.0f);
                float dx = wx - tt * e0x, dy = wy - tt * e0y;
                float dd = dx * dx + dy * dy;
                wx = px - Bx; wy = py - By;
                tt = fminf(fmaxf((wx * e1x + wy * e1y) * i1, 0.0f), 1.0f);
                dx = wx - tt * e1x; dy = wy - tt * e1y;
                dd = fminf(dd, dx * dx + dy * dy);
                wx = px - Cx; wy = py - Cy;
                tt = fminf(fmaxf((wx * e2x + wy * e2y) * i2, 0.0f), 1.0f);
                dx = wx - tt * e2x; dy = wy - tt * e2y;
                dd = fminf(dd, dx * dx + dy * dy);

                if (inside || dd <= 9.00001f) {
                    float dist = sqrtf(dd + 1e-12f);   // exact: matches ref
                    if (inside || dist <= 3.0f) {
                        int slot = atomicAdd(&s_count, 1);
                        if (slot < CAP)
                            s_key[slot] =
                                ((unsigned long long)__float_as_uint(dist) << 32)
                                | (unsigned)(iy * Ws + ix);
                    }
                }
            }
            __syncthreads();
            const int count = min(s_count, CAP);
            const float inv = 1.0f / st;

            // ---- O(count) two-level histogram select of 64 smallest ----
            int pb = 256, sb = 256, r2 = 0;   // defaults: count<=64 -> all
            if (count > 64) {
                s_hist[tid] = 0;
                __syncthreads();
                for (int e = tid; e < count; e += NT)
                    atomicAdd(&s_hist[(int)((s_key[e] >> 55) & 0xFF)], 1);
                __syncthreads();
                if (tid < 32) {
                    int bb, cc;
                    pivot_from_hist(s_hist, 63, lane, bb, cc);
                    if (lane == 0) { s_pb = bb; s_n1 = cc; }
                }
                __syncthreads();
                pb = s_pb;
                const int need = 64 - s_n1;       // 1..hist[pb]
                const int hpb  = s_hist[pb];
                __syncthreads();                   // hist reads before reuse
                if (hpb > need) {
                    s_hist[tid] = 0;
                    __syncthreads();
                    for (int e = tid; e < count; e += NT) {
                        unsigned long long k = s_key[e];
                        if ((int)((k >> 55) & 0xFF) == pb)
                            atomicAdd(&s_hist[(int)((k >> 47) & 0xFF)], 1);
                    }
                    __syncthreads();
                    if (tid < 32) {
                        int bb, cc;
                        pivot_from_hist(s_hist, need - 1, lane, bb, cc);
                        if (lane == 0) { s_sb = bb; s_n2 = cc; }
                    }
                    __syncthreads();
                    sb = s_sb;
                    r2 = need - s_n2;              // 1..subhist[sb]
                }
                // else: bin pb fits exactly (hpb == need): sb=256 selects all
            }

            float regA = 0.0f, clsA = 0.0f, objA = 0.0f;
            int nv = 0, nn = 0;

            for (int e = tid; e < count; e += NT) {
                const unsigned long long ke = s_key[e];
                const int eB = (int)((ke >> 55) & 0xFF);
                bool sel;
                if (eB != pb) sel = (eB < pb);
                else {
                    const int mB = (int)((ke >> 47) & 0xFF);
                    if (mB != sb) sel = (mB < sb);
                    else {
                        // exact rank among same-(pb,sb) keys (tiny set)
                        const unsigned long long hi = ke >> 47;
                        int rank = 0;
                        for (int j = 0; j < count; j++) {
                            unsigned long long kj = s_key[j];
                            rank += (kj < ke) && ((kj >> 47) == hi);
                        }
                        sel = (rank < r2);
                    }
                }
                if (sel) {
                    const int ie = (int)(ke & 0xffffffffu);
                    nv++;
                    clsA += fast_sp(-cls[(size_t)b * HW + ie]);

                    int ix = ie & (Ws - 1), iy = ie >> lg;
                    float ax = (ix + 0.5f) * st;
                    float ay = (iy + 0.5f) * st;
                    float g0x = (Ax - ax) * inv, g0y = (Ay - ay) * inv;
                    float g1x = (Bx - ax) * inv, g1y = (By - ay) * inv;
                    float g2x = (Cx - ax) * inv, g2y = (Cy - ay) * inv;

                    const float* rb = reg + (size_t)b * 6 * HW + ie;
                    float p0x = fminf(fmaxf(rb[0],            -64.0f), 64.0f);
                    float p0y = fminf(fmaxf(rb[(size_t)HW],   -64.0f), 64.0f);
                    float p1x = fminf(fmaxf(rb[(size_t)2*HW], -64.0f), 64.0f);
                    float p1y = fminf(fmaxf(rb[(size_t)3*HW], -64.0f), 64.0f);
                    float p2x = fminf(fmaxf(rb[(size_t)4*HW], -64.0f), 64.0f);
                    float p2y = fminf(fmaxf(rb[(size_t)5*HW], -64.0f), 64.0f);

                    float p0 = (p0x - g0x) * (p0x - g0x)
                             + (p0y - g0y) * (p0y - g0y);
                    float d11 = sqrtf((p1x-g1x)*(p1x-g1x) + (p1y-g1y)*(p1y-g1y));
                    float d12 = sqrtf((p1x-g2x)*(p1x-g2x) + (p1y-g2y)*(p1y-g2y));
                    float d21 = sqrtf((p2x-g1x)*(p2x-g1x) + (p2y-g1y)*(p2y-g1y));
                    float d22 = sqrtf((p2x-g2x)*(p2x-g2x) + (p2y-g2y)*(p2y-g2y));
                    float cd = fminf(d11, d12) + fminf(d21, d22)
                             + fminf(d11, d21) + fminf(d12, d22);
                    regA += p0 + cd;

                    int cell = markBase + ie;
                    unsigned bit = 1u << (cell & 31);
                    unsigned old = atomicOr(&g_bits[cell >> 5], bit);
                    if (!(old & bit)) {
                        float x = obj[(size_t)b * HW + ie];
                        objA += 1.2f * fast_sp(-x) - fast_sp(x);
                        nn++;
                    }
                }
            }
            acc[0] += (double)regA;
            acc[1] += (double)clsA;
            acc[2] += (double)objA;
            acc[3] += (double)nv;
            acc[4] += (double)nn;
        }

        if (tid == 0) s_task = atomicAdd(&g_task, 1);
        __syncthreads();          // fences s_key reads; s_task visible
        t = s_task;
    }

    // ================= block reduce -> per-block partials =================
#pragma unroll
    for (int c = 0; c < 5; c++) {
        double v = acc[c];
#pragma unroll
        for (int o = 16; o > 0; o >>= 1)
            v += __shfl_down_sync(0xffffffffu, v, o);
        if (lane == 0) s_w[wid][c] = v;
    }
    __syncthreads();
    if (wid == 0) {
#pragma unroll
        for (int c = 0; c < 5; c++) {
            double v = (lane < 8) ? s_w[lane][c] : 0.0;
#pragma unroll
            for (int o = 4; o > 0; o >>= 1)
                v += __shfl_down_sync(0xffffffffu, v, o);
            if (lane == 0) g_part[bid][c] = v;
        }
    }

    // ================= grid barrier =================
    if (tid == 0) {
        __threadfence();
        atomicAdd(&g_arrive, 1);
        while (*(volatile int*)&g_arrive < GRID) __nanosleep(32);
        __threadfence();
    }
    __syncthreads();

    // ================= Phase 2: finalize + cleanup =================
    if (bid == 0) {
        double v[5];
#pragma unroll
        for (int c = 0; c < 5; c++) v[c] = 0.0;
        for (int i = tid; i < GRID; i += NT)
#pragma unroll
            for (int c = 0; c < 5; c++) v[c] += g_part[i][c];
#pragma unroll
        for (int c = 0; c < 5; c++) {
            double r = v[c];
#pragma unroll
            for (int o = 16; o > 0; o >>= 1)
                r += __shfl_down_sync(0xffffffffu, r, o);
            if (lane == 0) s_w[wid][c] = r;
        }
        __syncthreads();
        if (tid == 0) {
            double tot[5];
#pragma unroll
            for (int c = 0; c < 5; c++) {
                double r = 0.0;
                for (int w = 0; w < 8; w++) r += s_w[w][c];
                tot[c] = r;
            }
            double pos_eps = fmax(tot[3], 1.0);
            double neg = fmax((double)TOTAL_CELLS - tot[4], 1.0);
            double total = tot[0] / pos_eps
                         + tot[2] / (pos_eps + neg)
                         + tot[1] / pos_eps;
            float tt = (float)total;
            out[0] = isfinite(tt) ? tt : 0.0f;
        }
    } else {
        for (int i = (bid - 1) * NT + tid; i < NBITS; i += (GRID - 1) * NT)
            g_bits[i] = 0u;
    }

    // ================= exit barrier: reset queue state =================
    __syncthreads();
    if (tid == 0) {
        __threadfence();
        int r = atomicAdd(&g_exit, 1);
        if (r == GRID - 1) { g_task = GRID; g_arrive = 0; g_exit = 0; }
    }
}

extern "C" void kernel_launch(void* const* d_in, const int* in_sizes, int n_in,
                              void* d_out, int out_size) {
    (void)in_sizes; (void)n_in; (void)out_size;
    fused_kernel<<<GRID, NT>>>(
        (const float*)d_in[0], (const float*)d_in[1], (const float*)d_in[2],
        (const float*)d_in[3], (const float*)d_in[4], (const float*)d_in[5],
        (const float*)d_in[6], (const float*)d_in[7], (const float*)d_in[8],
        (const float*)d_in[9], (float*)d_out);
}